// round 4
// baseline (speedup 1.0000x reference)
#include <cuda_runtime.h>
#include <math.h>

#define T_TOK 512
#define D_DIM 1024
#define E_EXP 64
#define F_INT 512
#define TOPK  4

// ---------------- persistent device scratch (no allocations allowed) ----------
__device__ float g_logits[T_TOK * E_EXP];
__device__ float g_topk_w[T_TOK * TOPK];
__device__ int   g_exp_cnt[E_EXP];
__device__ int   g_exp_tok[E_EXP * T_TOK];          // packed entry = token*4 + slot
__device__ float g_H[T_TOK * TOPK * F_INT];         // 4 MB  per (token,slot) hidden
__device__ float g_Y[T_TOK * TOPK * D_DIM];         // 8 MB  per (token,slot) down-proj

// ---------------- 0: zero expert counts --------------------------------------
__global__ void zero_kernel() { g_exp_cnt[threadIdx.x] = 0; }

// ---------------- 1: router logits  C[512,64] = X @ Gw^T ---------------------
__global__ __launch_bounds__(256) void logits_kernel(
    const float* __restrict__ x, const float* __restrict__ gw)
{
    const int tblk = blockIdx.x * 16;
    const int tid  = threadIdx.x;
    __shared__ __align__(16) float As[32][20];
    __shared__ __align__(16) float Bs[32][68];
    const int ttok = (tid >> 5) << 1;   // 0,2,...,14
    const int te   = (tid & 31) << 1;   // 0..62
    float acc00 = 0.f, acc01 = 0.f, acc10 = 0.f, acc11 = 0.f;

    for (int k0 = 0; k0 < D_DIM; k0 += 32) {
        if (tid < 128) {
            int tok = tid >> 3, kk4 = tid & 7;
            float4 v = *(const float4*)(x + (size_t)(tblk + tok) * D_DIM + k0 + (kk4 << 2));
            As[(kk4 << 2) + 0][tok] = v.x;
            As[(kk4 << 2) + 1][tok] = v.y;
            As[(kk4 << 2) + 2][tok] = v.z;
            As[(kk4 << 2) + 3][tok] = v.w;
        }
#pragma unroll
        for (int j = 0; j < 2; j++) {
            int idx = tid + (j << 8);
            int r = idx >> 3, kk4 = idx & 7;
            float4 v = *(const float4*)(gw + (size_t)r * D_DIM + k0 + (kk4 << 2));
            Bs[(kk4 << 2) + 0][r] = v.x;
            Bs[(kk4 << 2) + 1][r] = v.y;
            Bs[(kk4 << 2) + 2][r] = v.z;
            Bs[(kk4 << 2) + 3][r] = v.w;
        }
        __syncthreads();
#pragma unroll
        for (int kk = 0; kk < 32; kk++) {
            float a0 = As[kk][ttok], a1 = As[kk][ttok + 1];
            float b0 = Bs[kk][te],   b1 = Bs[kk][te + 1];
            acc00 += a0 * b0; acc01 += a0 * b1;
            acc10 += a1 * b0; acc11 += a1 * b1;
        }
        __syncthreads();
    }
    g_logits[(size_t)(tblk + ttok)     * E_EXP + te]     = acc00;
    g_logits[(size_t)(tblk + ttok)     * E_EXP + te + 1] = acc01;
    g_logits[(size_t)(tblk + ttok + 1) * E_EXP + te]     = acc10;
    g_logits[(size_t)(tblk + ttok + 1) * E_EXP + te + 1] = acc11;
}

// ---------------- 2: per-token top-4 + renorm + expert lists ------------------
__global__ void topk_kernel()
{
    const int t = blockIdx.x;
    const int lane = threadIdx.x;
    float c0 = g_logits[t * E_EXP + lane];
    float c1 = g_logits[t * E_EXP + lane + 32];
    float selv[4]; int seli[4];
#pragma unroll
    for (int s = 0; s < 4; s++) {
        float bv; int bi;
        if (c0 >= c1) { bv = c0; bi = lane; } else { bv = c1; bi = lane + 32; }
#pragma unroll
        for (int off = 16; off > 0; off >>= 1) {
            float ov = __shfl_xor_sync(0xffffffffu, bv, off);
            int   oi = __shfl_xor_sync(0xffffffffu, bi, off);
            if (ov > bv || (ov == bv && oi < bi)) { bv = ov; bi = oi; }
        }
        selv[s] = bv; seli[s] = bi;
        if (bi == lane)      c0 = -3.0e38f;
        if (bi == lane + 32) c1 = -3.0e38f;
    }
    if (lane == 0) {
        // softmax denom over all E cancels under top-k renorm:
        // w_s = exp(l_s - max) / sum_top4 exp(l_j - max)
        float m = selv[0];
        float ew[4]; float sum = 0.f;
#pragma unroll
        for (int s = 0; s < 4; s++) { ew[s] = expf(selv[s] - m); sum += ew[s]; }
        float inv = 1.f / sum;
#pragma unroll
        for (int s = 0; s < 4; s++) {
            g_topk_w[t * 4 + s] = ew[s] * inv;
            int ee = seli[s];
            int pos = atomicAdd(&g_exp_cnt[ee], 1);
            g_exp_tok[ee * T_TOK + pos] = t * 4 + s;
        }
    }
}

// ---------------- 3: Stage A — gate/up GEMM + SiLU (grouped, gathered) --------
// CTA = (fchunk 0..7, expert). Tile: 32 tokens x (64 gate | 64 up), K = 1024.
__global__ __launch_bounds__(256) void stageA_kernel(
    const float* __restrict__ x,
    const float* __restrict__ wg,
    const float* __restrict__ wu)
{
    const int e = blockIdx.y;
    const int fchunk = blockIdx.x;
    const int cnt = g_exp_cnt[e];
    if (cnt == 0) return;
    const int tid = threadIdx.x;

    __shared__ __align__(16) float As[32][36];
    __shared__ __align__(16) float Bs[32][132];
    __shared__ float Cg[32][65];
    __shared__ int ent[32];

    const float* wgBase = wg + ((size_t)e * F_INT + fchunk * 64) * D_DIM;
    const float* wuBase = wu + ((size_t)e * F_INT + fchunk * 64) * D_DIM;

    const int ttok = tid >> 5;   // 0..7   (4 tokens each)
    const int tn   = tid & 31;   // 0..31  (4 n each; n<64 gate, n>=64 up)
    const int tokL = tid >> 3;   // 0..31  (A-load row)
    const int kk4L = tid & 7;

    for (int base = 0; base < cnt; base += 32) {
        __syncthreads();
        if (tid < 32) {
            int i = base + tid;
            ent[tid] = (i < cnt) ? g_exp_tok[e * T_TOK + i] : -1;
        }
        __syncthreads();

        const int entL = ent[tokL];
        const bool validL = (entL >= 0);
        const float* xrow = validL ? (x + (size_t)(entL >> 2) * D_DIM) : x;

        float acc[4][4];
#pragma unroll
        for (int i = 0; i < 4; i++)
#pragma unroll
            for (int j = 0; j < 4; j++) acc[i][j] = 0.f;

        for (int k0 = 0; k0 < D_DIM; k0 += 32) {
            float4 av = make_float4(0.f, 0.f, 0.f, 0.f);
            if (validL) av = *(const float4*)(xrow + k0 + (kk4L << 2));
            As[(kk4L << 2) + 0][tokL] = av.x;
            As[(kk4L << 2) + 1][tokL] = av.y;
            As[(kk4L << 2) + 2][tokL] = av.z;
            As[(kk4L << 2) + 3][tokL] = av.w;
#pragma unroll
            for (int j = 0; j < 4; j++) {
                int idx = tid + (j << 8);
                int r = idx >> 3, kk4 = idx & 7;
                const float* src = (r < 64) ? (wgBase + (size_t)r * D_DIM)
                                            : (wuBase + (size_t)(r - 64) * D_DIM);
                float4 bv = *(const float4*)(src + k0 + (kk4 << 2));
                Bs[(kk4 << 2) + 0][r] = bv.x;
                Bs[(kk4 << 2) + 1][r] = bv.y;
                Bs[(kk4 << 2) + 2][r] = bv.z;
                Bs[(kk4 << 2) + 3][r] = bv.w;
            }
            __syncthreads();
#pragma unroll
            for (int kk = 0; kk < 32; kk++) {
                float4 a = *(const float4*)&As[kk][ttok << 2];
                float4 b = *(const float4*)&Bs[kk][tn << 2];
                acc[0][0] += a.x * b.x; acc[0][1] += a.x * b.y; acc[0][2] += a.x * b.z; acc[0][3] += a.x * b.w;
                acc[1][0] += a.y * b.x; acc[1][1] += a.y * b.y; acc[1][2] += a.y * b.z; acc[1][3] += a.y * b.w;
                acc[2][0] += a.z * b.x; acc[2][1] += a.z * b.y; acc[2][2] += a.z * b.z; acc[2][3] += a.z * b.w;
                acc[3][0] += a.w * b.x; acc[3][1] += a.w * b.y; acc[3][2] += a.w * b.z; acc[3][3] += a.w * b.w;
            }
            __syncthreads();
        }

        // gate threads (tn<16) publish g; up threads (tn>=16) fuse silu(g)*u
        if (tn < 16) {
#pragma unroll
            for (int i = 0; i < 4; i++)
#pragma unroll
                for (int j = 0; j < 4; j++)
                    Cg[(ttok << 2) + i][(tn << 2) + j] = acc[i][j];
        }
        __syncthreads();
        if (tn >= 16) {
            const int fb = (tn - 16) << 2;
#pragma unroll
            for (int i = 0; i < 4; i++) {
                int ec = ent[(ttok << 2) + i];
                if (ec < 0) continue;
                float g0 = Cg[(ttok << 2) + i][fb + 0];
                float g1 = Cg[(ttok << 2) + i][fb + 1];
                float g2 = Cg[(ttok << 2) + i][fb + 2];
                float g3 = Cg[(ttok << 2) + i][fb + 3];
                float4 hv;
                hv.x = g0 / (1.f + __expf(-g0)) * acc[i][0];
                hv.y = g1 / (1.f + __expf(-g1)) * acc[i][1];
                hv.z = g2 / (1.f + __expf(-g2)) * acc[i][2];
                hv.w = g3 / (1.f + __expf(-g3)) * acc[i][3];
                *(float4*)(g_H + (size_t)ec * F_INT + fchunk * 64 + fb) = hv;
            }
        }
    }
}

// ---------------- 4: Stage B — down GEMM into per-(token,slot) Y --------------
// CTA = (dchunk 0..7, expert). Tile: 32 tokens x 128 d, K = 512.
__global__ __launch_bounds__(256) void stageB_kernel(const float* __restrict__ wd)
{
    const int e = blockIdx.y;
    const int dchunk = blockIdx.x;
    const int cnt = g_exp_cnt[e];
    if (cnt == 0) return;
    const int tid = threadIdx.x;

    __shared__ __align__(16) float As[32][36];
    __shared__ __align__(16) float Bs[32][132];
    __shared__ int ent[32];

    const float* wdBase = wd + ((size_t)e * D_DIM + dchunk * 128) * F_INT;
    const int ttok = tid >> 5, tn = tid & 31, tokL = tid >> 3, kk4L = tid & 7;

    for (int base = 0; base < cnt; base += 32) {
        __syncthreads();
        if (tid < 32) {
            int i = base + tid;
            ent[tid] = (i < cnt) ? g_exp_tok[e * T_TOK + i] : -1;
        }
        __syncthreads();

        const int entL = ent[tokL];
        const bool validL = (entL >= 0);
        const float* hrow = validL ? (g_H + (size_t)entL * F_INT) : g_H;

        float acc[4][4];
#pragma unroll
        for (int i = 0; i < 4; i++)
#pragma unroll
            for (int j = 0; j < 4; j++) acc[i][j] = 0.f;

        for (int k0 = 0; k0 < F_INT; k0 += 32) {
            float4 av = make_float4(0.f, 0.f, 0.f, 0.f);
            if (validL) av = *(const float4*)(hrow + k0 + (kk4L << 2));
            As[(kk4L << 2) + 0][tokL] = av.x;
            As[(kk4L << 2) + 1][tokL] = av.y;
            As[(kk4L << 2) + 2][tokL] = av.z;
            As[(kk4L << 2) + 3][tokL] = av.w;
#pragma unroll
            for (int j = 0; j < 4; j++) {
                int idx = tid + (j << 8);
                int r = idx >> 3, kk4 = idx & 7;
                float4 bv = *(const float4*)(wdBase + (size_t)r * F_INT + k0 + (kk4 << 2));
                Bs[(kk4 << 2) + 0][r] = bv.x;
                Bs[(kk4 << 2) + 1][r] = bv.y;
                Bs[(kk4 << 2) + 2][r] = bv.z;
                Bs[(kk4 << 2) + 3][r] = bv.w;
            }
            __syncthreads();
#pragma unroll
            for (int kk = 0; kk < 32; kk++) {
                float4 a = *(const float4*)&As[kk][ttok << 2];
                float4 b = *(const float4*)&Bs[kk][tn << 2];
                acc[0][0] += a.x * b.x; acc[0][1] += a.x * b.y; acc[0][2] += a.x * b.z; acc[0][3] += a.x * b.w;
                acc[1][0] += a.y * b.x; acc[1][1] += a.y * b.y; acc[1][2] += a.y * b.z; acc[1][3] += a.y * b.w;
                acc[2][0] += a.z * b.x; acc[2][1] += a.z * b.y; acc[2][2] += a.z * b.z; acc[2][3] += a.z * b.w;
                acc[3][0] += a.w * b.x; acc[3][1] += a.w * b.y; acc[3][2] += a.w * b.z; acc[3][3] += a.w * b.w;
            }
            __syncthreads();
        }
#pragma unroll
        for (int i = 0; i < 4; i++) {
            int ec = ent[(ttok << 2) + i];
            if (ec < 0) continue;
            float4 yv = make_float4(acc[i][0], acc[i][1], acc[i][2], acc[i][3]);
            *(float4*)(g_Y + (size_t)ec * D_DIM + dchunk * 128 + (tn << 2)) = yv;
        }
    }
}

// ---------------- 5: weighted combine out[t,d] = sum_s w * Y[t,s,d] ----------
__global__ void combine_kernel(float* __restrict__ out)
{
    const int t = blockIdx.x;
    const int d = threadIdx.x << 2;
    const float w0 = g_topk_w[t * 4 + 0];
    const float w1 = g_topk_w[t * 4 + 1];
    const float w2 = g_topk_w[t * 4 + 2];
    const float w3 = g_topk_w[t * 4 + 3];
    const float* yb = g_Y + (size_t)t * 4 * D_DIM;
    float4 y0 = *(const float4*)(yb + 0 * D_DIM + d);
    float4 y1 = *(const float4*)(yb + 1 * D_DIM + d);
    float4 y2 = *(const float4*)(yb + 2 * D_DIM + d);
    float4 y3 = *(const float4*)(yb + 3 * D_DIM + d);
    float4 o;
    o.x = w0 * y0.x + w1 * y1.x + w2 * y2.x + w3 * y3.x;
    o.y = w0 * y0.y + w1 * y1.y + w2 * y2.y + w3 * y3.y;
    o.z = w0 * y0.z + w1 * y1.z + w2 * y2.z + w3 * y3.z;
    o.w = w0 * y0.w + w1 * y1.w + w2 * y2.w + w3 * y3.w;
    *(float4*)(out + (size_t)t * D_DIM + d) = o;
}

// ---------------- launch ------------------------------------------------------
extern "C" void kernel_launch(void* const* d_in, const int* in_sizes, int n_in,
                              void* d_out, int out_size)
{
    (void)in_sizes; (void)n_in; (void)out_size;
    const float* x  = (const float*)d_in[0];  // hidden_states [512,1024]
    const float* gw = (const float*)d_in[1];  // gate_w        [64,1024]
    const float* wg = (const float*)d_in[2];  // w_gate        [64,512,1024]
    const float* wu = (const float*)d_in[3];  // w_up          [64,512,1024]
    const float* wd = (const float*)d_in[4];  // w_down        [64,1024,512]
    float* out = (float*)d_out;               // [512,1024] f32

    zero_kernel   <<<1, 64>>>();
    logits_kernel <<<32, 256>>>(x, gw);
    topk_kernel   <<<T_TOK, 32>>>();
    stageA_kernel <<<dim3(8, E_EXP), 256>>>(x, wg, wu);
    stageB_kernel <<<dim3(8, E_EXP), 256>>>(wd);
    combine_kernel<<<T_TOK, 256>>>(out);
}

// round 8
// speedup vs baseline: 2.2340x; 2.2340x over previous
#include <cuda_runtime.h>
#include <cuda_bf16.h>
#include <math.h>
#include <stdint.h>

#define T_TOK 512
#define D_DIM 1024
#define E_EXP 64
#define F_INT 512
#define TOPK  4

#define ROWB 144   // 64 bf16 = 128B data + 16B pad: conflict-free ldmatrix & swizzle-free

// ---------------- persistent device scratch ----------------------------------
__device__ float g_logits[T_TOK * E_EXP];
__device__ float g_topk_w[T_TOK * TOPK];
__device__ int   g_exp_cnt[E_EXP];
__device__ int   g_exp_tok[E_EXP * T_TOK];                 // entry = token*4 + slot
__device__ __nv_bfloat16 g_Hhi[T_TOK * TOPK * F_INT];      // 2 MB
__device__ __nv_bfloat16 g_Hlo[T_TOK * TOPK * F_INT];      // 2 MB
__device__ float g_Y[T_TOK * TOPK * D_DIM];                // 8 MB

// ---------------- helpers -----------------------------------------------------
__device__ __forceinline__ uint32_t smem_u32(const void* p) {
    uint32_t a;
    asm("{ .reg .u64 t; cvta.to.shared.u64 t, %1; cvt.u32.u64 %0, t; }" : "=r"(a) : "l"(p));
    return a;
}
__device__ __forceinline__ void ldm4(uint32_t* r, uint32_t a) {
    asm volatile("ldmatrix.sync.aligned.m8n8.x4.shared.b16 {%0,%1,%2,%3}, [%4];"
        : "=r"(r[0]), "=r"(r[1]), "=r"(r[2]), "=r"(r[3]) : "r"(a));
}
__device__ __forceinline__ void mma16816(float* d, const uint32_t* a, const uint32_t* b) {
    asm volatile("mma.sync.aligned.m16n8k16.row.col.f32.bf16.bf16.f32 "
        "{%0,%1,%2,%3}, {%4,%5,%6,%7}, {%8,%9}, {%0,%1,%2,%3};"
        : "+f"(d[0]), "+f"(d[1]), "+f"(d[2]), "+f"(d[3])
        : "r"(a[0]), "r"(a[1]), "r"(a[2]), "r"(a[3]), "r"(b[0]), "r"(b[1]));
}
__device__ __forceinline__ uint32_t pack_bf2(__nv_bfloat16 a, __nv_bfloat16 b) {
    return (uint32_t)__bfloat16_as_ushort(a) | ((uint32_t)__bfloat16_as_ushort(b) << 16);
}
// split fp32x4 into bf16 hi + bf16 lo residual, store 8B each
__device__ __forceinline__ void cvt_split_sts(float4 v, char* phi, char* plo) {
    __nv_bfloat16 hx = __float2bfloat16(v.x), hy = __float2bfloat16(v.y);
    __nv_bfloat16 hz = __float2bfloat16(v.z), hw = __float2bfloat16(v.w);
    uint2 h = make_uint2(pack_bf2(hx, hy), pack_bf2(hz, hw));
    __nv_bfloat16 lx = __float2bfloat16(v.x - __bfloat162float(hx));
    __nv_bfloat16 ly = __float2bfloat16(v.y - __bfloat162float(hy));
    __nv_bfloat16 lz = __float2bfloat16(v.z - __bfloat162float(hz));
    __nv_bfloat16 lw = __float2bfloat16(v.w - __bfloat162float(hw));
    uint2 l = make_uint2(pack_bf2(lx, ly), pack_bf2(lz, lw));
    *(uint2*)phi = h;
    *(uint2*)plo = l;
}
// 4 float4 per thread of a [128 x 64] fp32 chunk
__device__ __forceinline__ void ldgW(float4* v, const float* base, int ld, int k0, int id0) {
#pragma unroll
    for (int j = 0; j < 4; j++) {
        int id = id0 + (j << 8);
        int r = id >> 4, q = id & 15;
        v[j] = *(const float4*)(base + (size_t)r * ld + k0 + (q << 2));
    }
}
__device__ __forceinline__ void stsW(const float4* v, char* hi, char* lo, int id0) {
#pragma unroll
    for (int j = 0; j < 4; j++) {
        int id = id0 + (j << 8);
        int r = id >> 4, q = id & 15;
        int off = r * ROWB + (q << 3);
        cvt_split_sts(v[j], hi + off, lo + off);
    }
}

// ---------------- 0: zero expert counts --------------------------------------
__global__ void zero_kernel() { g_exp_cnt[threadIdx.x] = 0; }

// ---------------- 1: router logits  C[512,64] = X @ Gw^T ---------------------
__global__ __launch_bounds__(256) void logits_kernel(
    const float* __restrict__ x, const float* __restrict__ gw)
{
    const int tblk = blockIdx.x * 16;
    const int tid  = threadIdx.x;
    __shared__ __align__(16) float As[32][20];
    __shared__ __align__(16) float Bs[32][68];
    const int ttok = (tid >> 5) << 1;
    const int te   = (tid & 31) << 1;
    float acc00 = 0.f, acc01 = 0.f, acc10 = 0.f, acc11 = 0.f;

    for (int k0 = 0; k0 < D_DIM; k0 += 32) {
        if (tid < 128) {
            int tok = tid >> 3, kk4 = tid & 7;
            float4 v = *(const float4*)(x + (size_t)(tblk + tok) * D_DIM + k0 + (kk4 << 2));
            As[(kk4 << 2) + 0][tok] = v.x;
            As[(kk4 << 2) + 1][tok] = v.y;
            As[(kk4 << 2) + 2][tok] = v.z;
            As[(kk4 << 2) + 3][tok] = v.w;
        }
#pragma unroll
        for (int j = 0; j < 2; j++) {
            int idx = tid + (j << 8);
            int r = idx >> 3, kk4 = idx & 7;
            float4 v = *(const float4*)(gw + (size_t)r * D_DIM + k0 + (kk4 << 2));
            Bs[(kk4 << 2) + 0][r] = v.x;
            Bs[(kk4 << 2) + 1][r] = v.y;
            Bs[(kk4 << 2) + 2][r] = v.z;
            Bs[(kk4 << 2) + 3][r] = v.w;
        }
        __syncthreads();
#pragma unroll
        for (int kk = 0; kk < 32; kk++) {
            float a0 = As[kk][ttok], a1 = As[kk][ttok + 1];
            float b0 = Bs[kk][te],   b1 = Bs[kk][te + 1];
            acc00 += a0 * b0; acc01 += a0 * b1;
            acc10 += a1 * b0; acc11 += a1 * b1;
        }
        __syncthreads();
    }
    g_logits[(size_t)(tblk + ttok)     * E_EXP + te]     = acc00;
    g_logits[(size_t)(tblk + ttok)     * E_EXP + te + 1] = acc01;
    g_logits[(size_t)(tblk + ttok + 1) * E_EXP + te]     = acc10;
    g_logits[(size_t)(tblk + ttok + 1) * E_EXP + te + 1] = acc11;
}

// ---------------- 2: per-token top-4 + renorm + expert lists ------------------
__global__ void topk_kernel()
{
    const int t = blockIdx.x;
    const int lane = threadIdx.x;
    float c0 = g_logits[t * E_EXP + lane];
    float c1 = g_logits[t * E_EXP + lane + 32];
    float selv[4]; int seli[4];
#pragma unroll
    for (int s = 0; s < 4; s++) {
        float bv; int bi;
        if (c0 >= c1) { bv = c0; bi = lane; } else { bv = c1; bi = lane + 32; }
#pragma unroll
        for (int off = 16; off > 0; off >>= 1) {
            float ov = __shfl_xor_sync(0xffffffffu, bv, off);
            int   oi = __shfl_xor_sync(0xffffffffu, bi, off);
            if (ov > bv || (ov == bv && oi < bi)) { bv = ov; bi = oi; }
        }
        selv[s] = bv; seli[s] = bi;
        if (bi == lane)      c0 = -3.0e38f;
        if (bi == lane + 32) c1 = -3.0e38f;
    }
    if (lane == 0) {
        float m = selv[0];
        float ew[4]; float sum = 0.f;
#pragma unroll
        for (int s = 0; s < 4; s++) { ew[s] = expf(selv[s] - m); sum += ew[s]; }
        float inv = 1.f / sum;
#pragma unroll
        for (int s = 0; s < 4; s++) {
            g_topk_w[t * 4 + s] = ew[s] * inv;
            int ee = seli[s];
            int pos = atomicAdd(&g_exp_cnt[ee], 1);
            g_exp_tok[ee * T_TOK + pos] = t * 4 + s;
        }
    }
}

// ---------------- 3: Stage A — HMMA gate/up GEMM + in-register SiLU -----------
// CTA = (fchunk 0..3, expert). Out tile [128 f x 32 tok] for gate AND up.
// Warp w owns f-rows 16w..16w+15 of both, so silu(g)*u is elementwise in regs.
#define OFF_AGH 0
#define OFF_AGL 18432
#define OFF_AUH 36864
#define OFF_AUL 55296
#define OFF_BH  73728
#define OFF_BL  78336
#define BUF_A   82944

__device__ __forceinline__ void kstepA(uint32_t cb, int s, int a_off, int b_off,
                                       float* accg, float* accu)
{
    const int so = s << 5;
    uint32_t agh[4], agl[4], auh[4], aul[4];
    ldm4(agh, cb + OFF_AGH + a_off + so);
    ldm4(agl, cb + OFF_AGL + a_off + so);
    ldm4(auh, cb + OFF_AUH + a_off + so);
    ldm4(aul, cb + OFF_AUL + a_off + so);
    uint32_t bh[8], bl[8];
    ldm4(bh,     cb + OFF_BH + b_off + so);
    ldm4(bh + 4, cb + OFF_BH + b_off + 16 * ROWB + so);
    ldm4(bl,     cb + OFF_BL + b_off + so);
    ldm4(bl + 4, cb + OFF_BL + b_off + 16 * ROWB + so);
#pragma unroll
    for (int nt = 0; nt < 4; nt++) {
        mma16816(accg + nt * 4, agh, bh + nt * 2);
        mma16816(accg + nt * 4, agl, bh + nt * 2);
        mma16816(accg + nt * 4, agh, bl + nt * 2);
        mma16816(accu + nt * 4, auh, bh + nt * 2);
        mma16816(accu + nt * 4, aul, bh + nt * 2);
        mma16816(accu + nt * 4, auh, bl + nt * 2);
    }
}

__global__ __launch_bounds__(256) void stageA_mma(
    const float* __restrict__ x,
    const float* __restrict__ wg,
    const float* __restrict__ wu)
{
    const int e = blockIdx.y, fc = blockIdx.x;
    const int cnt = g_exp_cnt[e];
    if (cnt == 0) return;
    extern __shared__ __align__(16) char dsm[];
    __shared__ int ent[32];
    const int tid = threadIdx.x, wid = tid >> 5, lane = tid & 31;
    const uint32_t smA = smem_u32(dsm);

    const float* wgB = wg + ((size_t)e * F_INT + fc * 128) * D_DIM;
    const float* wuB = wu + ((size_t)e * F_INT + fc * 128) * D_DIM;

    // ldmatrix per-lane address offsets (bytes)
    const int a_off = ((wid << 4) + (lane & 15)) * ROWB + ((lane >> 4) << 4);
    const int b_off = (((lane >> 4) << 3) + (lane & 7)) * ROWB + (((lane >> 3) & 1) << 4);

    for (int base = 0; base < cnt; base += 32) {
        __syncthreads();
        if (tid < 32) ent[tid] = (base + tid < cnt) ? g_exp_tok[e * T_TOK + base + tid] : -1;
        __syncthreads();

        {   // prologue: chunk 0 -> buffer 0
            char* B0 = dsm;
            float4 v[4];
            ldgW(v, wgB, D_DIM, 0, tid);        stsW(v, B0 + OFF_AGH, B0 + OFF_AGL, tid);
            ldgW(v, wgB, D_DIM, 0, tid + 1024); stsW(v, B0 + OFF_AGH, B0 + OFF_AGL, tid + 1024);
            ldgW(v, wuB, D_DIM, 0, tid);        stsW(v, B0 + OFF_AUH, B0 + OFF_AUL, tid);
            ldgW(v, wuB, D_DIM, 0, tid + 1024); stsW(v, B0 + OFF_AUH, B0 + OFF_AUL, tid + 1024);
            int r = tid >> 3, q = tid & 7;
            int en_ = ent[r];
#pragma unroll
            for (int j = 0; j < 2; j++) {
                int c = (q << 1) + j;
                float4 bv = (en_ >= 0)
                    ? *(const float4*)(x + (size_t)(en_ >> 2) * D_DIM + (c << 2))
                    : make_float4(0.f, 0.f, 0.f, 0.f);
                int off = r * ROWB + (c << 3);
                cvt_split_sts(bv, B0 + OFF_BH + off, B0 + OFF_BL + off);
            }
        }
        float accg[16], accu[16];
#pragma unroll
        for (int i = 0; i < 16; i++) { accg[i] = 0.f; accu[i] = 0.f; }

        for (int kt = 0; kt < 16; kt++) {
            __syncthreads();                       // buffer kt&1 ready; prev reads of other buf done
            const uint32_t cb = smA + (uint32_t)((kt & 1) * BUF_A);
            char* NB = dsm + ((kt + 1) & 1) * BUF_A;
            const bool more = (kt < 15);
            const int k0n = (kt + 1) << 6;

            kstepA(cb, 0, a_off, b_off, accg, accu);
            float4 v0[4];
            if (more) ldgW(v0, wgB, D_DIM, k0n, tid);
            kstepA(cb, 1, a_off, b_off, accg, accu);
            if (more) {
                stsW(v0, NB + OFF_AGH, NB + OFF_AGL, tid);
                ldgW(v0, wgB, D_DIM, k0n, tid + 1024);
            }
            kstepA(cb, 2, a_off, b_off, accg, accu);
            if (more) {
                stsW(v0, NB + OFF_AGH, NB + OFF_AGL, tid + 1024);
                ldgW(v0, wuB, D_DIM, k0n, tid);
            }
            kstepA(cb, 3, a_off, b_off, accg, accu);
            if (more) {
                stsW(v0, NB + OFF_AUH, NB + OFF_AUL, tid);
                ldgW(v0, wuB, D_DIM, k0n, tid + 1024);
                stsW(v0, NB + OFF_AUH, NB + OFF_AUL, tid + 1024);
                int r = tid >> 3, q = tid & 7;
                int en_ = ent[r];
#pragma unroll
                for (int j = 0; j < 2; j++) {
                    int c = (q << 1) + j;
                    float4 bv = (en_ >= 0)
                        ? *(const float4*)(x + (size_t)(en_ >> 2) * D_DIM + k0n + (c << 2))
                        : make_float4(0.f, 0.f, 0.f, 0.f);
                    int off = r * ROWB + (c << 3);
                    cvt_split_sts(bv, NB + OFF_BH + off, NB + OFF_BL + off);
                }
            }
        }

        // epilogue: silu(g)*u in regs -> smem transpose -> coalesced bf16 hi/lo
        __syncthreads();
        float* sm_h = (float*)dsm;
        {
            const int r0 = (wid << 4) + (lane >> 2);
            const int c0 = (lane & 3) << 1;
#pragma unroll
            for (int nt = 0; nt < 4; nt++) {
                int t0 = (nt << 3) + c0;
#pragma unroll
                for (int q = 0; q < 4; q++) {
                    int f = r0 + ((q >> 1) << 3);
                    int t = t0 + (q & 1);
                    float g = accg[nt * 4 + q], u = accu[nt * 4 + q];
                    float h = g / (1.f + __expf(-g)) * u;
                    sm_h[t * 132 + f] = h;
                }
            }
        }
        __syncthreads();
        {
            const int tt = tid >> 3, seg = tid & 7;
            const int ec = ent[tt];
            if (ec >= 0) {
                const float* src = sm_h + tt * 132 + (seg << 4);
                uint32_t hp[8], lp[8];
#pragma unroll
                for (int i = 0; i < 8; i++) {
                    float a = src[2 * i], b2 = src[2 * i + 1];
                    __nv_bfloat16 ha = __float2bfloat16(a), hb = __float2bfloat16(b2);
                    hp[i] = pack_bf2(ha, hb);
                    lp[i] = pack_bf2(__float2bfloat16(a  - __bfloat162float(ha)),
                                     __float2bfloat16(b2 - __bfloat162float(hb)));
                }
                uint4* dh = (uint4*)(g_Hhi + (size_t)ec * F_INT + fc * 128 + (seg << 4));
                uint4* dl = (uint4*)(g_Hlo + (size_t)ec * F_INT + fc * 128 + (seg << 4));
                dh[0] = make_uint4(hp[0], hp[1], hp[2], hp[3]);
                dh[1] = make_uint4(hp[4], hp[5], hp[6], hp[7]);
                dl[0] = make_uint4(lp[0], lp[1], lp[2], lp[3]);
                dl[1] = make_uint4(lp[4], lp[5], lp[6], lp[7]);
            }
        }
    }
}

// ---------------- 4: Stage B — HMMA down GEMM --------------------------------
// CTA = (dchunk 0..7, expert). Out tile [128 d x 32 tok], K = 512.
#define OFF_ADH 0
#define OFF_ADL 18432
#define OFF_BBH 36864
#define OFF_BBL 41472
#define BUF_B   46080

__device__ __forceinline__ void kstepB(uint32_t cb, int s, int a_off, int b_off, float* acc)
{
    const int so = s << 5;
    uint32_t adh[4], adl[4], bh[8], bl[8];
    ldm4(adh, cb + OFF_ADH + a_off + so);
    ldm4(adl, cb + OFF_ADL + a_off + so);
    ldm4(bh,     cb + OFF_BBH + b_off + so);
    ldm4(bh + 4, cb + OFF_BBH + b_off + 16 * ROWB + so);
    ldm4(bl,     cb + OFF_BBL + b_off + so);
    ldm4(bl + 4, cb + OFF_BBL + b_off + 16 * ROWB + so);
#pragma unroll
    for (int nt = 0; nt < 4; nt++) {
        mma16816(acc + nt * 4, adh, bh + nt * 2);
        mma16816(acc + nt * 4, adl, bh + nt * 2);
        mma16816(acc + nt * 4, adh, bl + nt * 2);
    }
}

__global__ __launch_bounds__(256) void stageB_mma(const float* __restrict__ wd)
{
    const int e = blockIdx.y, dc = blockIdx.x;
    const int cnt = g_exp_cnt[e];
    if (cnt == 0) return;
    extern __shared__ __align__(16) char dsm[];
    __shared__ int ent[32];
    const int tid = threadIdx.x, wid = tid >> 5, lane = tid & 31;
    const uint32_t smA = smem_u32(dsm);

    const float* wdB = wd + ((size_t)e * D_DIM + dc * 128) * F_INT;
    const int a_off = ((wid << 4) + (lane & 15)) * ROWB + ((lane >> 4) << 4);
    const int b_off = (((lane >> 4) << 3) + (lane & 7)) * ROWB + (((lane >> 3) & 1) << 4);

    for (int base = 0; base < cnt; base += 32) {
        __syncthreads();
        if (tid < 32) ent[tid] = (base + tid < cnt) ? g_exp_tok[e * T_TOK + base + tid] : -1;
        __syncthreads();

        {   // prologue: chunk 0 -> buffer 0
            char* B0 = dsm;
            float4 v[4];
            ldgW(v, wdB, F_INT, 0, tid);        stsW(v, B0 + OFF_ADH, B0 + OFF_ADL, tid);
            ldgW(v, wdB, F_INT, 0, tid + 1024); stsW(v, B0 + OFF_ADH, B0 + OFF_ADL, tid + 1024);
            int r = tid >> 3, q = tid & 7;
            int en_ = ent[r];
            uint4 vh = make_uint4(0, 0, 0, 0), vl = make_uint4(0, 0, 0, 0);
            if (en_ >= 0) {
                vh = *(const uint4*)(g_Hhi + (size_t)en_ * F_INT + (q << 3));
                vl = *(const uint4*)(g_Hlo + (size_t)en_ * F_INT + (q << 3));
            }
            int off = r * ROWB + (q << 4);
            *(uint4*)(B0 + OFF_BBH + off) = vh;
            *(uint4*)(B0 + OFF_BBL + off) = vl;
        }
        float acc[16];
#pragma unroll
        for (int i = 0; i < 16; i++) acc[i] = 0.f;

        for (int kt = 0; kt < 8; kt++) {
            __syncthreads();
            const uint32_t cb = smA + (uint32_t)((kt & 1) * BUF_B);
            char* NB = dsm + ((kt + 1) & 1) * BUF_B;
            const bool more = (kt < 7);
            const int k0n = (kt + 1) << 6;

            kstepB(cb, 0, a_off, b_off, acc);
            float4 v0[4];
            if (more) ldgW(v0, wdB, F_INT, k0n, tid);
            kstepB(cb, 1, a_off, b_off, acc);
            if (more) {
                stsW(v0, NB + OFF_ADH, NB + OFF_ADL, tid);
                ldgW(v0, wdB, F_INT, k0n, tid + 1024);
            }
            kstepB(cb, 2, a_off, b_off, acc);
            if (more) stsW(v0, NB + OFF_ADH, NB + OFF_ADL, tid + 1024);
            kstepB(cb, 3, a_off, b_off, acc);
            if (more) {
                int r = tid >> 3, q = tid & 7;
                int en_ = ent[r];
                uint4 vh = make_uint4(0, 0, 0, 0), vl = make_uint4(0, 0, 0, 0);
                if (en_ >= 0) {
                    vh = *(const uint4*)(g_Hhi + (size_t)en_ * F_INT + k0n + (q << 3));
                    vl = *(const uint4*)(g_Hlo + (size_t)en_ * F_INT + k0n + (q << 3));
                }
                int off = r * ROWB + (q << 4);
                *(uint4*)(NB + OFF_BBH + off) = vh;
                *(uint4*)(NB + OFF_BBL + off) = vl;
            }
        }

        // epilogue: smem transpose -> coalesced f32 writeout
        __syncthreads();
        float* sm_y = (float*)dsm;
        {
            const int r0 = (wid << 4) + (lane >> 2);
            const int c0 = (lane & 3) << 1;
#pragma unroll
            for (int nt = 0; nt < 4; nt++) {
                int t0 = (nt << 3) + c0;
#pragma unroll
                for (int q = 0; q < 4; q++) {
                    int d = r0 + ((q >> 1) << 3);
                    int t = t0 + (q & 1);
                    sm_y[t * 132 + d] = acc[nt * 4 + q];
                }
            }
        }
        __syncthreads();
        {
            const int tt = tid >> 3, seg = tid & 7;
            const int ec = ent[tt];
            if (ec >= 0) {
                const float* src = sm_y + tt * 132 + (seg << 4);
                float* dst = g_Y + (size_t)ec * D_DIM + dc * 128 + (seg << 4);
#pragma unroll
                for (int i = 0; i < 4; i++)
                    *(float4*)(dst + (i << 2)) = *(const float4*)(src + (i << 2));
            }
        }
    }
}

// ---------------- 5: weighted combine ----------------------------------------
__global__ void combine_kernel(float* __restrict__ out)
{
    const int t = blockIdx.x;
    const int d = threadIdx.x << 2;
    const float w0 = g_topk_w[t * 4 + 0];
    const float w1 = g_topk_w[t * 4 + 1];
    const float w2 = g_topk_w[t * 4 + 2];
    const float w3 = g_topk_w[t * 4 + 3];
    const float* yb = g_Y + (size_t)t * 4 * D_DIM;
    float4 y0 = *(const float4*)(yb + 0 * D_DIM + d);
    float4 y1 = *(const float4*)(yb + 1 * D_DIM + d);
    float4 y2 = *(const float4*)(yb + 2 * D_DIM + d);
    float4 y3 = *(const float4*)(yb + 3 * D_DIM + d);
    float4 o;
    o.x = w0 * y0.x + w1 * y1.x + w2 * y2.x + w3 * y3.x;
    o.y = w0 * y0.y + w1 * y1.y + w2 * y2.y + w3 * y3.y;
    o.z = w0 * y0.z + w1 * y1.z + w2 * y2.z + w3 * y3.z;
    o.w = w0 * y0.w + w1 * y1.w + w2 * y2.w + w3 * y3.w;
    *(float4*)(out + (size_t)t * D_DIM + d) = o;
}

// ---------------- launch ------------------------------------------------------
extern "C" void kernel_launch(void* const* d_in, const int* in_sizes, int n_in,
                              void* d_out, int out_size)
{
    (void)in_sizes; (void)n_in; (void)out_size;
    const float* x  = (const float*)d_in[0];
    const float* gw = (const float*)d_in[1];
    const float* wg = (const float*)d_in[2];
    const float* wu = (const float*)d_in[3];
    const float* wd = (const float*)d_in[4];
    float* out = (float*)d_out;

    const int smemA = 2 * BUF_A;   // 165888
    const int smemB = 2 * BUF_B;   //  92160
    cudaFuncSetAttribute(stageA_mma, cudaFuncAttributeMaxDynamicSharedMemorySize, smemA);
    cudaFuncSetAttribute(stageB_mma, cudaFuncAttributeMaxDynamicSharedMemorySize, smemB);

    zero_kernel   <<<1, 64>>>();
    logits_kernel <<<32, 256>>>(x, gw);
    topk_kernel   <<<T_TOK, 32>>>();
    stageA_mma    <<<dim3(4, E_EXP), 256, smemA>>>(x, wg, wu);
    stageB_mma    <<<dim3(8, E_EXP), 256, smemB>>>(wd);
    combine_kernel<<<T_TOK, 256>>>(out);
}

// round 9
// speedup vs baseline: 2.5365x; 1.1354x over previous
#include <cuda_runtime.h>
#include <cuda_bf16.h>
#include <math.h>
#include <stdint.h>

#define T_TOK 512
#define D_DIM 1024
#define E_EXP 64
#define F_INT 512
#define TOPK  4

#define ROWB 144   // 64 bf16 = 128B data + 16B pad: conflict-free ldmatrix, swizzle-free

// ---------------- persistent device scratch ----------------------------------
__device__ float g_logits[T_TOK * E_EXP];
__device__ float g_topk_w[T_TOK * TOPK];
__device__ int   g_exp_cnt[E_EXP];
__device__ int   g_exp_tok[E_EXP * T_TOK];                 // entry = token*4 + slot
__device__ __nv_bfloat16 g_Hhi[T_TOK * TOPK * F_INT];      // 2 MB
__device__ __nv_bfloat16 g_Hlo[T_TOK * TOPK * F_INT];      // 2 MB
__device__ float g_Y[T_TOK * TOPK * D_DIM];                // 8 MB

// ---------------- helpers -----------------------------------------------------
__device__ __forceinline__ uint32_t smem_u32(const void* p) {
    uint32_t a;
    asm("{ .reg .u64 t; cvta.to.shared.u64 t, %1; cvt.u32.u64 %0, t; }" : "=r"(a) : "l"(p));
    return a;
}
__device__ __forceinline__ void ldm4(uint32_t* r, uint32_t a) {
    asm volatile("ldmatrix.sync.aligned.m8n8.x4.shared.b16 {%0,%1,%2,%3}, [%4];"
        : "=r"(r[0]), "=r"(r[1]), "=r"(r[2]), "=r"(r[3]) : "r"(a));
}
__device__ __forceinline__ void mma16816(float* d, const uint32_t* a, const uint32_t* b) {
    asm volatile("mma.sync.aligned.m16n8k16.row.col.f32.bf16.bf16.f32 "
        "{%0,%1,%2,%3}, {%4,%5,%6,%7}, {%8,%9}, {%0,%1,%2,%3};"
        : "+f"(d[0]), "+f"(d[1]), "+f"(d[2]), "+f"(d[3])
        : "r"(a[0]), "r"(a[1]), "r"(a[2]), "r"(a[3]), "r"(b[0]), "r"(b[1]));
}
__device__ __forceinline__ uint32_t pack_bf2(__nv_bfloat16 a, __nv_bfloat16 b) {
    return (uint32_t)__bfloat16_as_ushort(a) | ((uint32_t)__bfloat16_as_ushort(b) << 16);
}
// split fp32x4 into bf16 hi + bf16 lo residual, store 8B each
__device__ __forceinline__ void cvt_split_sts(float4 v, char* phi, char* plo) {
    __nv_bfloat16 hx = __float2bfloat16(v.x), hy = __float2bfloat16(v.y);
    __nv_bfloat16 hz = __float2bfloat16(v.z), hw = __float2bfloat16(v.w);
    uint2 h = make_uint2(pack_bf2(hx, hy), pack_bf2(hz, hw));
    __nv_bfloat16 lx = __float2bfloat16(v.x - __bfloat162float(hx));
    __nv_bfloat16 ly = __float2bfloat16(v.y - __bfloat162float(hy));
    __nv_bfloat16 lz = __float2bfloat16(v.z - __bfloat162float(hz));
    __nv_bfloat16 lw = __float2bfloat16(v.w - __bfloat162float(hw));
    uint2 l = make_uint2(pack_bf2(lx, ly), pack_bf2(lz, lw));
    *(uint2*)phi = h;
    *(uint2*)plo = l;
}
// 512-thread variants: 4 float4/thread over a [128 x 64] fp32 chunk
__device__ __forceinline__ void ldgW512(float4* v, const float* base, int ld, int k0, int tid) {
#pragma unroll
    for (int j = 0; j < 4; j++) {
        int id = tid + (j << 9);
        int r = id >> 4, q = id & 15;
        v[j] = *(const float4*)(base + (size_t)r * ld + k0 + (q << 2));
    }
}
__device__ __forceinline__ void stsW512(const float4* v, char* hi, char* lo, int tid) {
#pragma unroll
    for (int j = 0; j < 4; j++) {
        int id = tid + (j << 9);
        int r = id >> 4, q = id & 15;
        int off = r * ROWB + (q << 3);
        cvt_split_sts(v[j], hi + off, lo + off);
    }
}

// ---------------- 0: zero expert counts --------------------------------------
__global__ void zero_kernel() { g_exp_cnt[threadIdx.x] = 0; }

// ---------------- 1: router logits  C[512,64] = X @ Gw^T ---------------------
__global__ __launch_bounds__(256) void logits_kernel(
    const float* __restrict__ x, const float* __restrict__ gw)
{
    const int tblk = blockIdx.x * 16;
    const int tid  = threadIdx.x;
    __shared__ __align__(16) float As[32][20];
    __shared__ __align__(16) float Bs[32][68];
    const int ttok = (tid >> 5) << 1;
    const int te   = (tid & 31) << 1;
    float acc00 = 0.f, acc01 = 0.f, acc10 = 0.f, acc11 = 0.f;

    for (int k0 = 0; k0 < D_DIM; k0 += 32) {
        if (tid < 128) {
            int tok = tid >> 3, kk4 = tid & 7;
            float4 v = *(const float4*)(x + (size_t)(tblk + tok) * D_DIM + k0 + (kk4 << 2));
            As[(kk4 << 2) + 0][tok] = v.x;
            As[(kk4 << 2) + 1][tok] = v.y;
            As[(kk4 << 2) + 2][tok] = v.z;
            As[(kk4 << 2) + 3][tok] = v.w;
        }
#pragma unroll
        for (int j = 0; j < 2; j++) {
            int idx = tid + (j << 8);
            int r = idx >> 3, kk4 = idx & 7;
            float4 v = *(const float4*)(gw + (size_t)r * D_DIM + k0 + (kk4 << 2));
            Bs[(kk4 << 2) + 0][r] = v.x;
            Bs[(kk4 << 2) + 1][r] = v.y;
            Bs[(kk4 << 2) + 2][r] = v.z;
            Bs[(kk4 << 2) + 3][r] = v.w;
        }
        __syncthreads();
#pragma unroll
        for (int kk = 0; kk < 32; kk++) {
            float a0 = As[kk][ttok], a1 = As[kk][ttok + 1];
            float b0 = Bs[kk][te],   b1 = Bs[kk][te + 1];
            acc00 += a0 * b0; acc01 += a0 * b1;
            acc10 += a1 * b0; acc11 += a1 * b1;
        }
        __syncthreads();
    }
    g_logits[(size_t)(tblk + ttok)     * E_EXP + te]     = acc00;
    g_logits[(size_t)(tblk + ttok)     * E_EXP + te + 1] = acc01;
    g_logits[(size_t)(tblk + ttok + 1) * E_EXP + te]     = acc10;
    g_logits[(size_t)(tblk + ttok + 1) * E_EXP + te + 1] = acc11;
}

// ---------------- 2: per-token top-4 + renorm + expert lists ------------------
__global__ void topk_kernel()
{
    const int t = blockIdx.x;
    const int lane = threadIdx.x;
    float c0 = g_logits[t * E_EXP + lane];
    float c1 = g_logits[t * E_EXP + lane + 32];
    float selv[4]; int seli[4];
#pragma unroll
    for (int s = 0; s < 4; s++) {
        float bv; int bi;
        if (c0 >= c1) { bv = c0; bi = lane; } else { bv = c1; bi = lane + 32; }
#pragma unroll
        for (int off = 16; off > 0; off >>= 1) {
            float ov = __shfl_xor_sync(0xffffffffu, bv, off);
            int   oi = __shfl_xor_sync(0xffffffffu, bi, off);
            if (ov > bv || (ov == bv && oi < bi)) { bv = ov; bi = oi; }
        }
        selv[s] = bv; seli[s] = bi;
        if (bi == lane)      c0 = -3.0e38f;
        if (bi == lane + 32) c1 = -3.0e38f;
    }
    if (lane == 0) {
        float m = selv[0];
        float ew[4]; float sum = 0.f;
#pragma unroll
        for (int s = 0; s < 4; s++) { ew[s] = expf(selv[s] - m); sum += ew[s]; }
        float inv = 1.f / sum;
#pragma unroll
        for (int s = 0; s < 4; s++) {
            g_topk_w[t * 4 + s] = ew[s] * inv;
            int ee = seli[s];
            int pos = atomicAdd(&g_exp_cnt[ee], 1);
            g_exp_tok[ee * T_TOK + pos] = t * 4 + s;
        }
    }
}

// ---------------- 3: Stage A — HMMA gate/up GEMM + in-register SiLU -----------
// CTA = (fchunk 0..3, expert), 512 threads, warp grid 8(M) x 2(N).
// Warp (wm, wn) owns out tile [16 f x 16 tok] of gate AND up.
#define OFF_AGH 0
#define OFF_AGL 18432
#define OFF_AUH 36864
#define OFF_AUL 55296
#define OFF_BH  73728
#define OFF_BL  78336
#define BUF_A   82944

__device__ __forceinline__ void kstepA(uint32_t cb, int s, int a_off, int b_off,
                                       float* accg, float* accu)
{
    const int so = s << 5;
    uint32_t agh[4], agl[4], auh[4], aul[4];
    ldm4(agh, cb + OFF_AGH + a_off + so);
    ldm4(agl, cb + OFF_AGL + a_off + so);
    ldm4(auh, cb + OFF_AUH + a_off + so);
    ldm4(aul, cb + OFF_AUL + a_off + so);
    uint32_t bh[4], bl[4];
    ldm4(bh, cb + OFF_BH + b_off + so);
    ldm4(bl, cb + OFF_BL + b_off + so);
#pragma unroll
    for (int nt = 0; nt < 2; nt++) {
        mma16816(accg + nt * 4, agh, bh + nt * 2);
        mma16816(accg + nt * 4, agl, bh + nt * 2);
        mma16816(accg + nt * 4, agh, bl + nt * 2);
        mma16816(accu + nt * 4, auh, bh + nt * 2);
        mma16816(accu + nt * 4, aul, bh + nt * 2);
        mma16816(accu + nt * 4, auh, bl + nt * 2);
    }
}

__global__ __launch_bounds__(512) void stageA_mma(
    const float* __restrict__ x,
    const float* __restrict__ wg,
    const float* __restrict__ wu)
{
    const int e = blockIdx.y, fc = blockIdx.x;
    const int cnt = g_exp_cnt[e];
    if (cnt == 0) return;
    extern __shared__ __align__(16) char dsm[];
    __shared__ int ent[32];
    const int tid = threadIdx.x, wid = tid >> 5, lane = tid & 31;
    const int wm = wid >> 1, wn = wid & 1;
    const uint32_t smA = smem_u32(dsm);

    const float* wgB = wg + ((size_t)e * F_INT + fc * 128) * D_DIM;
    const float* wuB = wu + ((size_t)e * F_INT + fc * 128) * D_DIM;

    const int a_off = ((wm << 4) + (lane & 15)) * ROWB + ((lane >> 4) << 4);
    const int b_off = ((wn << 4) + ((lane >> 4) << 3) + (lane & 7)) * ROWB
                    + (((lane >> 3) & 1) << 4);

    for (int base = 0; base < cnt; base += 32) {
        __syncthreads();
        if (tid < 32) ent[tid] = (base + tid < cnt) ? g_exp_tok[e * T_TOK + base + tid] : -1;
        __syncthreads();

        {   // prologue: chunk 0 -> buffer 0
            char* B0 = dsm;
            float4 v[4];
            ldgW512(v, wgB, D_DIM, 0, tid); stsW512(v, B0 + OFF_AGH, B0 + OFF_AGL, tid);
            ldgW512(v, wuB, D_DIM, 0, tid); stsW512(v, B0 + OFF_AUH, B0 + OFF_AUL, tid);
            int r = tid >> 4, q = tid & 15;
            int en_ = ent[r];
            float4 bv = (en_ >= 0)
                ? *(const float4*)(x + (size_t)(en_ >> 2) * D_DIM + (q << 2))
                : make_float4(0.f, 0.f, 0.f, 0.f);
            int off = r * ROWB + (q << 3);
            cvt_split_sts(bv, B0 + OFF_BH + off, B0 + OFF_BL + off);
        }
        float accg[8], accu[8];
#pragma unroll
        for (int i = 0; i < 8; i++) { accg[i] = 0.f; accu[i] = 0.f; }

        for (int kt = 0; kt < 16; kt++) {
            __syncthreads();
            const uint32_t cb = smA + (uint32_t)((kt & 1) * BUF_A);
            char* NB = dsm + ((kt + 1) & 1) * BUF_A;
            const bool more = (kt < 15);
            const int k0n = (kt + 1) << 6;

            kstepA(cb, 0, a_off, b_off, accg, accu);
            float4 v0[4];
            if (more) ldgW512(v0, wgB, D_DIM, k0n, tid);
            kstepA(cb, 1, a_off, b_off, accg, accu);
            if (more) {
                stsW512(v0, NB + OFF_AGH, NB + OFF_AGL, tid);
                ldgW512(v0, wuB, D_DIM, k0n, tid);
            }
            kstepA(cb, 2, a_off, b_off, accg, accu);
            if (more) stsW512(v0, NB + OFF_AUH, NB + OFF_AUL, tid);
            kstepA(cb, 3, a_off, b_off, accg, accu);
            if (more) {
                int r = tid >> 4, q = tid & 15;
                int en_ = ent[r];
                float4 bv = (en_ >= 0)
                    ? *(const float4*)(x + (size_t)(en_ >> 2) * D_DIM + k0n + (q << 2))
                    : make_float4(0.f, 0.f, 0.f, 0.f);
                int off = r * ROWB + (q << 3);
                cvt_split_sts(bv, NB + OFF_BH + off, NB + OFF_BL + off);
            }
        }

        // epilogue: silu(g)*u in regs -> smem transpose -> coalesced bf16 hi/lo
        __syncthreads();
        float* sm_h = (float*)dsm;
        {
            const int r0 = (wm << 4) + (lane >> 2);
            const int c0 = (wn << 4) + ((lane & 3) << 1);
#pragma unroll
            for (int nt = 0; nt < 2; nt++) {
                int t0 = c0 + (nt << 3);
#pragma unroll
                for (int q = 0; q < 4; q++) {
                    int f = r0 + ((q >> 1) << 3);
                    int t = t0 + (q & 1);
                    float g = accg[nt * 4 + q], u = accu[nt * 4 + q];
                    float h = g / (1.f + __expf(-g)) * u;
                    sm_h[t * 132 + f] = h;
                }
            }
        }
        __syncthreads();
        {
            const int tt = tid >> 4, seg = tid & 15;   // 32 tok x 16 segs of 8 floats
            const int ec = ent[tt];
            if (ec >= 0) {
                const float* src = sm_h + tt * 132 + (seg << 3);
                uint32_t hp[4], lp[4];
#pragma unroll
                for (int i = 0; i < 4; i++) {
                    float a = src[2 * i], b2 = src[2 * i + 1];
                    __nv_bfloat16 ha = __float2bfloat16(a), hb = __float2bfloat16(b2);
                    hp[i] = pack_bf2(ha, hb);
                    lp[i] = pack_bf2(__float2bfloat16(a  - __bfloat162float(ha)),
                                     __float2bfloat16(b2 - __bfloat162float(hb)));
                }
                *(uint4*)(g_Hhi + (size_t)ec * F_INT + fc * 128 + (seg << 3)) =
                    make_uint4(hp[0], hp[1], hp[2], hp[3]);
                *(uint4*)(g_Hlo + (size_t)ec * F_INT + fc * 128 + (seg << 3)) =
                    make_uint4(lp[0], lp[1], lp[2], lp[3]);
            }
        }
    }
}

// ---------------- 4: Stage B — HMMA down GEMM --------------------------------
// CTA = (dchunk 0..7, expert), 512 threads, 2 CTAs/SM. Warp tile [16 d x 16 tok].
#define OFF_ADH 0
#define OFF_ADL 18432
#define OFF_BBH 36864
#define OFF_BBL 41472
#define BUF_B   46080

__device__ __forceinline__ void kstepB(uint32_t cb, int s, int a_off, int b_off, float* acc)
{
    const int so = s << 5;
    uint32_t adh[4], adl[4], bh[4], bl[4];
    ldm4(adh, cb + OFF_ADH + a_off + so);
    ldm4(adl, cb + OFF_ADL + a_off + so);
    ldm4(bh,  cb + OFF_BBH + b_off + so);
    ldm4(bl,  cb + OFF_BBL + b_off + so);
#pragma unroll
    for (int nt = 0; nt < 2; nt++) {
        mma16816(acc + nt * 4, adh, bh + nt * 2);
        mma16816(acc + nt * 4, adl, bh + nt * 2);
        mma16816(acc + nt * 4, adh, bl + nt * 2);
    }
}

__global__ __launch_bounds__(512, 2) void stageB_mma(const float* __restrict__ wd)
{
    const int e = blockIdx.y, dc = blockIdx.x;
    const int cnt = g_exp_cnt[e];
    if (cnt == 0) return;
    extern __shared__ __align__(16) char dsm[];
    __shared__ int ent[32];
    const int tid = threadIdx.x, wid = tid >> 5, lane = tid & 31;
    const int wm = wid >> 1, wn = wid & 1;
    const uint32_t smA = smem_u32(dsm);

    const float* wdB = wd + ((size_t)e * D_DIM + dc * 128) * F_INT;
    const int a_off = ((wm << 4) + (lane & 15)) * ROWB + ((lane >> 4) << 4);
    const int b_off = ((wn << 4) + ((lane >> 4) << 3) + (lane & 7)) * ROWB
                    + (((lane >> 3) & 1) << 4);

    for (int base = 0; base < cnt; base += 32) {
        __syncthreads();
        if (tid < 32) ent[tid] = (base + tid < cnt) ? g_exp_tok[e * T_TOK + base + tid] : -1;
        __syncthreads();

        {   // prologue: chunk 0 -> buffer 0
            char* B0 = dsm;
            float4 v[4];
            ldgW512(v, wdB, F_INT, 0, tid); stsW512(v, B0 + OFF_ADH, B0 + OFF_ADL, tid);
            int idx = tid & 255, r = idx >> 3, q = idx & 7;
            int en_ = ent[r];
            uint4 vv = make_uint4(0, 0, 0, 0);
            const __nv_bfloat16* srcH = (tid < 256) ? g_Hhi : g_Hlo;
            if (en_ >= 0) vv = *(const uint4*)(srcH + (size_t)en_ * F_INT + (q << 3));
            char* dst = (tid < 256) ? (B0 + OFF_BBH) : (B0 + OFF_BBL);
            *(uint4*)(dst + r * ROWB + (q << 4)) = vv;
        }
        float acc[8];
#pragma unroll
        for (int i = 0; i < 8; i++) acc[i] = 0.f;

        for (int kt = 0; kt < 8; kt++) {
            __syncthreads();
            const uint32_t cb = smA + (uint32_t)((kt & 1) * BUF_B);
            char* NB = dsm + ((kt + 1) & 1) * BUF_B;
            const bool more = (kt < 7);
            const int k0n = (kt + 1) << 6;

            kstepB(cb, 0, a_off, b_off, acc);
            float4 v0[4];
            if (more) ldgW512(v0, wdB, F_INT, k0n, tid);
            kstepB(cb, 1, a_off, b_off, acc);
            if (more) stsW512(v0, NB + OFF_ADH, NB + OFF_ADL, tid);
            kstepB(cb, 2, a_off, b_off, acc);
            uint4 vv = make_uint4(0, 0, 0, 0);
            int r = 0, q = 0;
            if (more) {
                int idx = tid & 255; r = idx >> 3; q = idx & 7;
                int en_ = ent[r];
                const __nv_bfloat16* srcH = (tid < 256) ? g_Hhi : g_Hlo;
                if (en_ >= 0) vv = *(const uint4*)(srcH + (size_t)en_ * F_INT + k0n + (q << 3));
            }
            kstepB(cb, 3, a_off, b_off, acc);
            if (more) {
                char* dst = (tid < 256) ? (NB + OFF_BBH) : (NB + OFF_BBL);
                *(uint4*)(dst + r * ROWB + (q << 4)) = vv;
            }
        }

        // epilogue: smem transpose -> coalesced f32 writeout
        __syncthreads();
        float* sm_y = (float*)dsm;
        {
            const int r0 = (wm << 4) + (lane >> 2);
            const int c0 = (wn << 4) + ((lane & 3) << 1);
#pragma unroll
            for (int nt = 0; nt < 2; nt++) {
                int t0 = c0 + (nt << 3);
#pragma unroll
                for (int q = 0; q < 4; q++) {
                    int d = r0 + ((q >> 1) << 3);
                    int t = t0 + (q & 1);
                    sm_y[t * 132 + d] = acc[nt * 4 + q];
                }
            }
        }
        __syncthreads();
        {
            const int tt = tid >> 4, seg = tid & 15;
            const int ec = ent[tt];
            if (ec >= 0) {
                const float* src = sm_y + tt * 132 + (seg << 3);
                float* dst = g_Y + (size_t)ec * D_DIM + dc * 128 + (seg << 3);
                *(float4*)(dst)     = *(const float4*)(src);
                *(float4*)(dst + 4) = *(const float4*)(src + 4);
            }
        }
    }
}

// ---------------- 5: weighted combine ----------------------------------------
__global__ void combine_kernel(float* __restrict__ out)
{
    const int t = blockIdx.x;
    const int d = threadIdx.x << 2;
    const float w0 = g_topk_w[t * 4 + 0];
    const float w1 = g_topk_w[t * 4 + 1];
    const float w2 = g_topk_w[t * 4 + 2];
    const float w3 = g_topk_w[t * 4 + 3];
    const float* yb = g_Y + (size_t)t * 4 * D_DIM;
    float4 y0 = *(const float4*)(yb + 0 * D_DIM + d);
    float4 y1 = *(const float4*)(yb + 1 * D_DIM + d);
    float4 y2 = *(const float4*)(yb + 2 * D_DIM + d);
    float4 y3 = *(const float4*)(yb + 3 * D_DIM + d);
    float4 o;
    o.x = w0 * y0.x + w1 * y1.x + w2 * y2.x + w3 * y3.x;
    o.y = w0 * y0.y + w1 * y1.y + w2 * y2.y + w3 * y3.y;
    o.z = w0 * y0.z + w1 * y1.z + w2 * y2.z + w3 * y3.z;
    o.w = w0 * y0.w + w1 * y1.w + w2 * y2.w + w3 * y3.w;
    *(float4*)(out + (size_t)t * D_DIM + d) = o;
}

// ---------------- launch ------------------------------------------------------
extern "C" void kernel_launch(void* const* d_in, const int* in_sizes, int n_in,
                              void* d_out, int out_size)
{
    (void)in_sizes; (void)n_in; (void)out_size;
    const float* x  = (const float*)d_in[0];
    const float* gw = (const float*)d_in[1];
    const float* wg = (const float*)d_in[2];
    const float* wu = (const float*)d_in[3];
    const float* wd = (const float*)d_in[4];
    float* out = (float*)d_out;

    const int smemA = 2 * BUF_A;   // 165888 -> 1 CTA/SM, 16 warps
    const int smemB = 2 * BUF_B;   //  92160 -> 2 CTA/SM, 32 warps
    cudaFuncSetAttribute(stageA_mma, cudaFuncAttributeMaxDynamicSharedMemorySize, smemA);
    cudaFuncSetAttribute(stageB_mma, cudaFuncAttributeMaxDynamicSharedMemorySize, smemB);

    zero_kernel   <<<1, 64>>>();
    logits_kernel <<<32, 256>>>(x, gw);
    topk_kernel   <<<T_TOK, 32>>>();
    stageA_mma    <<<dim3(4, E_EXP), 512, smemA>>>(x, wg, wu);
    stageB_mma    <<<dim3(8, E_EXP), 512, smemB>>>(wd);
    combine_kernel<<<T_TOK, 256>>>(out);
}

// round 10
// speedup vs baseline: 2.7828x; 1.0971x over previous
#include <cuda_runtime.h>
#include <cuda_bf16.h>
#include <math.h>
#include <stdint.h>

#define T_TOK 512
#define D_DIM 1024
#define E_EXP 64
#define F_INT 512
#define TOPK  4

#define ROWB 144   // 64 bf16 = 128B data + 16B pad: conflict-free ldmatrix, swizzle-free

// ---------------- persistent device scratch ----------------------------------
__device__ float g_logits[T_TOK * E_EXP];
__device__ float g_topk_w[T_TOK * TOPK];
__device__ int   g_exp_cnt[E_EXP];
__device__ int   g_exp_tok[E_EXP * T_TOK];                 // entry = token*4 + slot
__device__ __nv_bfloat16 g_Hhi[T_TOK * TOPK * F_INT];      // 2 MB
__device__ __nv_bfloat16 g_Hlo[T_TOK * TOPK * F_INT];      // 2 MB
__device__ float g_Y[T_TOK * TOPK * D_DIM];                // 8 MB

// ---------------- helpers -----------------------------------------------------
__device__ __forceinline__ uint32_t smem_u32(const void* p) {
    uint32_t a;
    asm("{ .reg .u64 t; cvta.to.shared.u64 t, %1; cvt.u32.u64 %0, t; }" : "=r"(a) : "l"(p));
    return a;
}
__device__ __forceinline__ void ldm4(uint32_t* r, uint32_t a) {
    asm volatile("ldmatrix.sync.aligned.m8n8.x4.shared.b16 {%0,%1,%2,%3}, [%4];"
        : "=r"(r[0]), "=r"(r[1]), "=r"(r[2]), "=r"(r[3]) : "r"(a));
}
__device__ __forceinline__ void ldm2(uint32_t* r, uint32_t a) {
    asm volatile("ldmatrix.sync.aligned.m8n8.x2.shared.b16 {%0,%1}, [%2];"
        : "=r"(r[0]), "=r"(r[1]) : "r"(a));
}
__device__ __forceinline__ void mma16816(float* d, const uint32_t* a, const uint32_t* b) {
    asm volatile("mma.sync.aligned.m16n8k16.row.col.f32.bf16.bf16.f32 "
        "{%0,%1,%2,%3}, {%4,%5,%6,%7}, {%8,%9}, {%0,%1,%2,%3};"
        : "+f"(d[0]), "+f"(d[1]), "+f"(d[2]), "+f"(d[3])
        : "r"(a[0]), "r"(a[1]), "r"(a[2]), "r"(a[3]), "r"(b[0]), "r"(b[1]));
}
__device__ __forceinline__ uint32_t pack_bf2(__nv_bfloat16 a, __nv_bfloat16 b) {
    return (uint32_t)__bfloat16_as_ushort(a) | ((uint32_t)__bfloat16_as_ushort(b) << 16);
}
// split fp32x4 into bf16 hi + bf16 lo residual, store 8B each
__device__ __forceinline__ void cvt_split_sts(float4 v, char* phi, char* plo) {
    __nv_bfloat16 hx = __float2bfloat16(v.x), hy = __float2bfloat16(v.y);
    __nv_bfloat16 hz = __float2bfloat16(v.z), hw = __float2bfloat16(v.w);
    uint2 h = make_uint2(pack_bf2(hx, hy), pack_bf2(hz, hw));
    __nv_bfloat16 lx = __float2bfloat16(v.x - __bfloat162float(hx));
    __nv_bfloat16 ly = __float2bfloat16(v.y - __bfloat162float(hy));
    __nv_bfloat16 lz = __float2bfloat16(v.z - __bfloat162float(hz));
    __nv_bfloat16 lw = __float2bfloat16(v.w - __bfloat162float(hw));
    uint2 l = make_uint2(pack_bf2(lx, ly), pack_bf2(lz, lw));
    *(uint2*)phi = h;
    *(uint2*)plo = l;
}
// [64 x 64] fp32 chunk with 512 threads: 2 float4 per thread
__device__ __forceinline__ void ldgW64(float4* v, const float* base, int ld, int k0, int tid) {
#pragma unroll
    for (int j = 0; j < 2; j++) {
        int id = tid + (j << 9);
        int r = id >> 4, q = id & 15;
        v[j] = *(const float4*)(base + (size_t)r * ld + k0 + (q << 2));
    }
}
__device__ __forceinline__ void stsW64(const float4* v, char* hi, char* lo, int tid) {
#pragma unroll
    for (int j = 0; j < 2; j++) {
        int id = tid + (j << 9);
        int r = id >> 4, q = id & 15;
        int off = r * ROWB + (q << 3);
        cvt_split_sts(v[j], hi + off, lo + off);
    }
}

// ---------------- 1: router logits (block 0 also zeroes expert counts) --------
__global__ __launch_bounds__(256) void logits_kernel(
    const float* __restrict__ x, const float* __restrict__ gw)
{
    const int tblk = blockIdx.x * 16;
    const int tid  = threadIdx.x;
    if (blockIdx.x == 0 && tid < E_EXP) g_exp_cnt[tid] = 0;
    __shared__ __align__(16) float As[32][20];
    __shared__ __align__(16) float Bs[32][68];
    const int ttok = (tid >> 5) << 1;
    const int te   = (tid & 31) << 1;
    float acc00 = 0.f, acc01 = 0.f, acc10 = 0.f, acc11 = 0.f;

    for (int k0 = 0; k0 < D_DIM; k0 += 32) {
        if (tid < 128) {
            int tok = tid >> 3, kk4 = tid & 7;
            float4 v = *(const float4*)(x + (size_t)(tblk + tok) * D_DIM + k0 + (kk4 << 2));
            As[(kk4 << 2) + 0][tok] = v.x;
            As[(kk4 << 2) + 1][tok] = v.y;
            As[(kk4 << 2) + 2][tok] = v.z;
            As[(kk4 << 2) + 3][tok] = v.w;
        }
#pragma unroll
        for (int j = 0; j < 2; j++) {
            int idx = tid + (j << 8);
            int r = idx >> 3, kk4 = idx & 7;
            float4 v = *(const float4*)(gw + (size_t)r * D_DIM + k0 + (kk4 << 2));
            Bs[(kk4 << 2) + 0][r] = v.x;
            Bs[(kk4 << 2) + 1][r] = v.y;
            Bs[(kk4 << 2) + 2][r] = v.z;
            Bs[(kk4 << 2) + 3][r] = v.w;
        }
        __syncthreads();
#pragma unroll
        for (int kk = 0; kk < 32; kk++) {
            float a0 = As[kk][ttok], a1 = As[kk][ttok + 1];
            float b0 = Bs[kk][te],   b1 = Bs[kk][te + 1];
            acc00 += a0 * b0; acc01 += a0 * b1;
            acc10 += a1 * b0; acc11 += a1 * b1;
        }
        __syncthreads();
    }
    g_logits[(size_t)(tblk + ttok)     * E_EXP + te]     = acc00;
    g_logits[(size_t)(tblk + ttok)     * E_EXP + te + 1] = acc01;
    g_logits[(size_t)(tblk + ttok + 1) * E_EXP + te]     = acc10;
    g_logits[(size_t)(tblk + ttok + 1) * E_EXP + te + 1] = acc11;
}

// ---------------- 2: per-token top-4 + renorm + expert lists ------------------
__global__ void topk_kernel()
{
    const int t = blockIdx.x;
    const int lane = threadIdx.x;
    float c0 = g_logits[t * E_EXP + lane];
    float c1 = g_logits[t * E_EXP + lane + 32];
    float selv[4]; int seli[4];
#pragma unroll
    for (int s = 0; s < 4; s++) {
        float bv; int bi;
        if (c0 >= c1) { bv = c0; bi = lane; } else { bv = c1; bi = lane + 32; }
#pragma unroll
        for (int off = 16; off > 0; off >>= 1) {
            float ov = __shfl_xor_sync(0xffffffffu, bv, off);
            int   oi = __shfl_xor_sync(0xffffffffu, bi, off);
            if (ov > bv || (ov == bv && oi < bi)) { bv = ov; bi = oi; }
        }
        selv[s] = bv; seli[s] = bi;
        if (bi == lane)      c0 = -3.0e38f;
        if (bi == lane + 32) c1 = -3.0e38f;
    }
    if (lane == 0) {
        float m = selv[0];
        float ew[4]; float sum = 0.f;
#pragma unroll
        for (int s = 0; s < 4; s++) { ew[s] = expf(selv[s] - m); sum += ew[s]; }
        float inv = 1.f / sum;
#pragma unroll
        for (int s = 0; s < 4; s++) {
            g_topk_w[t * 4 + s] = ew[s] * inv;
            int ee = seli[s];
            int pos = atomicAdd(&g_exp_cnt[ee], 1);
            g_exp_tok[ee * T_TOK + pos] = t * 4 + s;
        }
    }
}

// ---------------- 3: Stage A — HMMA gate/up GEMM + in-register SiLU -----------
// CTA = (fchunk 0..7, expert), 512 threads, 2 CTAs/SM.
// Warp grid 4(M) x 4(N); warp tile [16 f x 8 tok] of gate AND up.
#define OFF_AGH 0
#define OFF_AGL 9216
#define OFF_AUH 18432
#define OFF_AUL 27648
#define OFF_BH  36864
#define OFF_BL  41472
#define BUF_A   46080

__device__ __forceinline__ void kstepA(uint32_t cb, int s, int a_off, int b_off,
                                       float* accg, float* accu)
{
    const int so = s << 5;
    uint32_t agh[4], agl[4], auh[4], aul[4];
    ldm4(agh, cb + OFF_AGH + a_off + so);
    ldm4(agl, cb + OFF_AGL + a_off + so);
    ldm4(auh, cb + OFF_AUH + a_off + so);
    ldm4(aul, cb + OFF_AUL + a_off + so);
    uint32_t bh[2], bl[2];
    ldm2(bh, cb + OFF_BH + b_off + so);
    ldm2(bl, cb + OFF_BL + b_off + so);
    mma16816(accg, agh, bh);
    mma16816(accg, agl, bh);
    mma16816(accg, agh, bl);
    mma16816(accu, auh, bh);
    mma16816(accu, aul, bh);
    mma16816(accu, auh, bl);
}

__global__ __launch_bounds__(512, 2) void stageA_mma(
    const float* __restrict__ x,
    const float* __restrict__ wg,
    const float* __restrict__ wu)
{
    const int e = blockIdx.y, fc = blockIdx.x;
    const int cnt = g_exp_cnt[e];
    if (cnt == 0) return;
    extern __shared__ __align__(16) char dsm[];
    __shared__ int ent[32];
    const int tid = threadIdx.x, wid = tid >> 5, lane = tid & 31;
    const int wm = wid >> 2, wn = wid & 3;
    const uint32_t smA = smem_u32(dsm);

    const float* wgB = wg + ((size_t)e * F_INT + fc * 64) * D_DIM;
    const float* wuB = wu + ((size_t)e * F_INT + fc * 64) * D_DIM;

    const int a_off = ((wm << 4) + (lane & 15)) * ROWB + ((lane >> 4) << 4);
    const int b_off = ((wn << 3) + (lane & 7)) * ROWB + (((lane >> 3) & 1) << 4);

    for (int base = 0; base < cnt; base += 32) {
        __syncthreads();
        if (tid < 32) ent[tid] = (base + tid < cnt) ? g_exp_tok[e * T_TOK + base + tid] : -1;
        __syncthreads();

        {   // prologue: chunk 0 -> buffer 0
            char* B0 = dsm;
            float4 v[2];
            ldgW64(v, wgB, D_DIM, 0, tid); stsW64(v, B0 + OFF_AGH, B0 + OFF_AGL, tid);
            ldgW64(v, wuB, D_DIM, 0, tid); stsW64(v, B0 + OFF_AUH, B0 + OFF_AUL, tid);
            int r = tid >> 4, q = tid & 15;
            int en_ = ent[r];
            float4 bv = (en_ >= 0)
                ? *(const float4*)(x + (size_t)(en_ >> 2) * D_DIM + (q << 2))
                : make_float4(0.f, 0.f, 0.f, 0.f);
            int off = r * ROWB + (q << 3);
            cvt_split_sts(bv, B0 + OFF_BH + off, B0 + OFF_BL + off);
        }
        float accg[4], accu[4];
#pragma unroll
        for (int i = 0; i < 4; i++) { accg[i] = 0.f; accu[i] = 0.f; }

        for (int kt = 0; kt < 16; kt++) {
            __syncthreads();
            const uint32_t cb = smA + (uint32_t)((kt & 1) * BUF_A);
            char* NB = dsm + ((kt + 1) & 1) * BUF_A;
            const bool more = (kt < 15);
            const int k0n = (kt + 1) << 6;

            kstepA(cb, 0, a_off, b_off, accg, accu);
            float4 vg[2], vu[2];
            if (more) ldgW64(vg, wgB, D_DIM, k0n, tid);
            kstepA(cb, 1, a_off, b_off, accg, accu);
            if (more) {
                stsW64(vg, NB + OFF_AGH, NB + OFF_AGL, tid);
                ldgW64(vu, wuB, D_DIM, k0n, tid);
            }
            kstepA(cb, 2, a_off, b_off, accg, accu);
            float4 bv = make_float4(0.f, 0.f, 0.f, 0.f);
            int offx = 0;
            if (more) {
                stsW64(vu, NB + OFF_AUH, NB + OFF_AUL, tid);
                int r = tid >> 4, q = tid & 15;
                int en_ = ent[r];
                if (en_ >= 0)
                    bv = *(const float4*)(x + (size_t)(en_ >> 2) * D_DIM + k0n + (q << 2));
                offx = r * ROWB + (q << 3);
            }
            kstepA(cb, 3, a_off, b_off, accg, accu);
            if (more) cvt_split_sts(bv, NB + OFF_BH + offx, NB + OFF_BL + offx);
        }

        // epilogue: silu(g)*u in regs -> smem transpose -> coalesced bf16 hi/lo
        __syncthreads();
        float* sm_h = (float*)dsm;
        {
            const int fr = (wm << 4) + (lane >> 2);
            const int tc = (wn << 3) + ((lane & 3) << 1);
#pragma unroll
            for (int q = 0; q < 4; q++) {
                int f = fr + ((q >> 1) << 3);
                int t = tc + (q & 1);
                float g = accg[q], u = accu[q];
                float h = g / (1.f + __expf(-g)) * u;
                sm_h[t * 132 + f] = h;
            }
        }
        __syncthreads();
        {
            const int tt = tid >> 4, seg = tid & 15;   // 32 tok x 16 segs of 4 floats
            const int ec = ent[tt];
            if (ec >= 0) {
                const float* src = sm_h + tt * 132 + (seg << 2);
                float a0 = src[0], a1 = src[1], a2 = src[2], a3 = src[3];
                __nv_bfloat16 h0 = __float2bfloat16(a0), h1 = __float2bfloat16(a1);
                __nv_bfloat16 h2 = __float2bfloat16(a2), h3 = __float2bfloat16(a3);
                uint2 hp = make_uint2(pack_bf2(h0, h1), pack_bf2(h2, h3));
                uint2 lp = make_uint2(
                    pack_bf2(__float2bfloat16(a0 - __bfloat162float(h0)),
                             __float2bfloat16(a1 - __bfloat162float(h1))),
                    pack_bf2(__float2bfloat16(a2 - __bfloat162float(h2)),
                             __float2bfloat16(a3 - __bfloat162float(h3))));
                *(uint2*)(g_Hhi + (size_t)ec * F_INT + fc * 64 + (seg << 2)) = hp;
                *(uint2*)(g_Hlo + (size_t)ec * F_INT + fc * 64 + (seg << 2)) = lp;
            }
        }
    }
}

// ---------------- 4: Stage B — HMMA down GEMM --------------------------------
// CTA = (dchunk 0..15, expert), 512 threads, 2 CTAs/SM. Warp tile [16 d x 8 tok].
#define OFF_ADH 0
#define OFF_ADL 9216
#define OFF_BBH 18432
#define OFF_BBL 23040
#define BUF_B   27648

__device__ __forceinline__ void kstepB(uint32_t cb, int s, int a_off, int b_off, float* acc)
{
    const int so = s << 5;
    uint32_t adh[4], adl[4], bh[2], bl[2];
    ldm4(adh, cb + OFF_ADH + a_off + so);
    ldm4(adl, cb + OFF_ADL + a_off + so);
    ldm2(bh,  cb + OFF_BBH + b_off + so);
    ldm2(bl,  cb + OFF_BBL + b_off + so);
    mma16816(acc, adh, bh);
    mma16816(acc, adl, bh);
    mma16816(acc, adh, bl);
}

__global__ __launch_bounds__(512, 2) void stageB_mma(const float* __restrict__ wd)
{
    const int e = blockIdx.y, dc = blockIdx.x;
    const int cnt = g_exp_cnt[e];
    if (cnt == 0) return;
    extern __shared__ __align__(16) char dsm[];
    __shared__ int ent[32];
    const int tid = threadIdx.x, wid = tid >> 5, lane = tid & 31;
    const int wm = wid >> 2, wn = wid & 3;
    const uint32_t smA = smem_u32(dsm);

    const float* wdB = wd + ((size_t)e * D_DIM + dc * 64) * F_INT;
    const int a_off = ((wm << 4) + (lane & 15)) * ROWB + ((lane >> 4) << 4);
    const int b_off = ((wn << 3) + (lane & 7)) * ROWB + (((lane >> 3) & 1) << 4);

    for (int base = 0; base < cnt; base += 32) {
        __syncthreads();
        if (tid < 32) ent[tid] = (base + tid < cnt) ? g_exp_tok[e * T_TOK + base + tid] : -1;
        __syncthreads();

        {   // prologue: chunk 0 -> buffer 0
            char* B0 = dsm;
            float4 v[2];
            ldgW64(v, wdB, F_INT, 0, tid); stsW64(v, B0 + OFF_ADH, B0 + OFF_ADL, tid);
            int idx = tid & 255, r = idx >> 3, q = idx & 7;
            int en_ = ent[r];
            uint4 vv = make_uint4(0, 0, 0, 0);
            const __nv_bfloat16* srcH = (tid < 256) ? g_Hhi : g_Hlo;
            if (en_ >= 0) vv = *(const uint4*)(srcH + (size_t)en_ * F_INT + (q << 3));
            char* dst = (tid < 256) ? (B0 + OFF_BBH) : (B0 + OFF_BBL);
            *(uint4*)(dst + r * ROWB + (q << 4)) = vv;
        }
        float acc[4];
#pragma unroll
        for (int i = 0; i < 4; i++) acc[i] = 0.f;

        for (int kt = 0; kt < 8; kt++) {
            __syncthreads();
            const uint32_t cb = smA + (uint32_t)((kt & 1) * BUF_B);
            char* NB = dsm + ((kt + 1) & 1) * BUF_B;
            const bool more = (kt < 7);
            const int k0n = (kt + 1) << 6;

            kstepB(cb, 0, a_off, b_off, acc);
            float4 v0[2];
            if (more) ldgW64(v0, wdB, F_INT, k0n, tid);
            kstepB(cb, 1, a_off, b_off, acc);
            if (more) stsW64(v0, NB + OFF_ADH, NB + OFF_ADL, tid);
            kstepB(cb, 2, a_off, b_off, acc);
            uint4 vv = make_uint4(0, 0, 0, 0);
            int r = 0, q = 0;
            if (more) {
                int idx = tid & 255; r = idx >> 3; q = idx & 7;
                int en_ = ent[r];
                const __nv_bfloat16* srcH = (tid < 256) ? g_Hhi : g_Hlo;
                if (en_ >= 0) vv = *(const uint4*)(srcH + (size_t)en_ * F_INT + k0n + (q << 3));
            }
            kstepB(cb, 3, a_off, b_off, acc);
            if (more) {
                char* dst = (tid < 256) ? (NB + OFF_BBH) : (NB + OFF_BBL);
                *(uint4*)(dst + r * ROWB + (q << 4)) = vv;
            }
        }

        // epilogue: smem transpose -> coalesced f32 writeout
        __syncthreads();
        float* sm_y = (float*)dsm;
        {
            const int dr = (wm << 4) + (lane >> 2);
            const int tc = (wn << 3) + ((lane & 3) << 1);
#pragma unroll
            for (int q = 0; q < 4; q++) {
                int d = dr + ((q >> 1) << 3);
                int t = tc + (q & 1);
                sm_y[t * 68 + d] = acc[q];
            }
        }
        __syncthreads();
        {
            const int tt = tid >> 4, seg = tid & 15;   // 32 tok x 16 segs of 4 floats
            const int ec = ent[tt];
            if (ec >= 0) {
                const float* src = sm_y + tt * 68 + (seg << 2);
                *(float4*)(g_Y + (size_t)ec * D_DIM + dc * 64 + (seg << 2)) =
                    make_float4(src[0], src[1], src[2], src[3]);
            }
        }
    }
}

// ---------------- 5: weighted combine ----------------------------------------
__global__ void combine_kernel(float* __restrict__ out)
{
    const int t = blockIdx.x;
    const int d = threadIdx.x << 2;
    const float w0 = g_topk_w[t * 4 + 0];
    const float w1 = g_topk_w[t * 4 + 1];
    const float w2 = g_topk_w[t * 4 + 2];
    const float w3 = g_topk_w[t * 4 + 3];
    const float* yb = g_Y + (size_t)t * 4 * D_DIM;
    float4 y0 = *(const float4*)(yb + 0 * D_DIM + d);
    float4 y1 = *(const float4*)(yb + 1 * D_DIM + d);
    float4 y2 = *(const float4*)(yb + 2 * D_DIM + d);
    float4 y3 = *(const float4*)(yb + 3 * D_DIM + d);
    float4 o;
    o.x = w0 * y0.x + w1 * y1.x + w2 * y2.x + w3 * y3.x;
    o.y = w0 * y0.y + w1 * y1.y + w2 * y2.y + w3 * y3.y;
    o.z = w0 * y0.z + w1 * y1.z + w2 * y2.z + w3 * y3.z;
    o.w = w0 * y0.w + w1 * y1.w + w2 * y2.w + w3 * y3.w;
    *(float4*)(out + (size_t)t * D_DIM + d) = o;
}

// ---------------- launch ------------------------------------------------------
extern "C" void kernel_launch(void* const* d_in, const int* in_sizes, int n_in,
                              void* d_out, int out_size)
{
    (void)in_sizes; (void)n_in; (void)out_size;
    const float* x  = (const float*)d_in[0];
    const float* gw = (const float*)d_in[1];
    const float* wg = (const float*)d_in[2];
    const float* wu = (const float*)d_in[3];
    const float* wd = (const float*)d_in[4];
    float* out = (float*)d_out;

    const int smemA = 2 * BUF_A;   // 92160 -> 2 CTAs/SM, 32 warps
    const int smemB = 2 * BUF_B;   // 55296 -> 2 CTAs/SM, 32 warps
    cudaFuncSetAttribute(stageA_mma, cudaFuncAttributeMaxDynamicSharedMemorySize, smemA);
    cudaFuncSetAttribute(stageB_mma, cudaFuncAttributeMaxDynamicSharedMemorySize, smemB);

    logits_kernel <<<32, 256>>>(x, gw);
    topk_kernel   <<<T_TOK, 32>>>();
    stageA_mma    <<<dim3(8, E_EXP), 512, smemA>>>(x, wg, wu);
    stageB_mma    <<<dim3(16, E_EXP), 512, smemB>>>(wd);
    combine_kernel<<<T_TOK, 256>>>(out);
}